// round 5
// baseline (speedup 1.0000x reference)
#include <cuda_runtime.h>
#include <math.h>

#define NN 8192
#define KK 32
#define DD 64
#define DID 32
#define BSZ 4
#define TT 8
#define DSCAN 1024

#define NT 8            // nodes per block
#define ROWS 32         // NT * BSZ rows per block
#define RP 34           // transposed-buffer row pitch (even, conflict-spread)

typedef unsigned long long ull;

// Persistent state (allocation-free scratch)
__device__ float g_h[BSZ * NN * DD];
__device__ float g_msgs[2][BSZ * NN * DD];
__device__ float g_wc[BSZ * NN * KK];
__device__ float g_ident[NN * DID];
__device__ float g_dw2p[256 * 128];   // dw2 padded 65 -> 128 cols
__device__ float g_db2p[128];

__device__ __forceinline__ float sigf(float x) { return 1.0f / (1.0f + __expf(-x)); }

__device__ __forceinline__ ull ffma2(ull a, ull b, ull c) {
    ull d;
    asm("fma.rn.f32x2 %0, %1, %2, %3;" : "=l"(d) : "l"(a), "l"(b), "l"(c));
    return d;
}
__device__ __forceinline__ ull pack2(float x) {
    ull p;
    unsigned u = __float_as_uint(x);
    asm("mov.b64 %0, {%1, %2};" : "=l"(p) : "r"(u), "r"(u));
    return p;
}
__device__ __forceinline__ float2 unpack2(ull p) {
    unsigned lo, hi;
    asm("mov.b64 {%0, %1}, %2;" : "=r"(lo), "=r"(hi) : "l"(p));
    return make_float2(__uint_as_float(lo), __uint_as_float(hi));
}
__device__ __forceinline__ ull repack(float x, float y) {
    ull p;
    unsigned a = __float_as_uint(x), b = __float_as_uint(y);
    asm("mov.b64 %0, {%1, %2};" : "=l"(p) : "r"(a), "r"(b));
    return p;
}

template <int CPT>
__device__ __forceinline__ void load_w(float* wv, const float* __restrict__ wr) {
    if (CPT == 4) {
        float4 f = __ldg(reinterpret_cast<const float4*>(wr));
        wv[0] = f.x; wv[1] = f.y; wv[2] = f.z; wv[3] = f.w;
    } else if (CPT == 2) {
        float2 f = __ldg(reinterpret_cast<const float2*>(wr));
        wv[0] = f.x; wv[1] = f.y;
    } else {
        wv[0] = __ldg(wr);
    }
}

// Yt[yoff+c][r] = act(sum_k Xt[k][r] * W[k][c] + b[c]).
// Xt transposed in smem (pitch RP). W plain row-major [CIN x COLS].
// 8 warps split COLS; lane = 4 row-groups x 8 col-groups; rows packed in f32x2.
// Weights software-pipelined: prefetch distance 2 k-iterations (hides L2 latency).
// ACT: 0 = none, 1 = silu, 2 = tanh
template <int CPT, int ACT, int CIN, int COLS>
__device__ __forceinline__ void gemmT(const float* Xt,
                                      const float* __restrict__ W,
                                      const float* __restrict__ bias,
                                      float* Yt, int yoff) {
    const int w = threadIdx.x >> 5;
    const int lane = threadIdx.x & 31;
    const int r0 = (lane >> 3) * 8;
    const int c0 = w * (COLS / 8) + (lane & 7) * CPT;
    ull acc[4][CPT];
#pragma unroll
    for (int p = 0; p < 4; p++)
#pragma unroll
        for (int j = 0; j < CPT; j++) acc[p][j] = 0ull;

    const float* xb = Xt + r0;
    const float* wb = W + c0;

    float w0[CPT], w1[CPT];
    load_w<CPT>(w0, wb);
    load_w<CPT>(w1, wb + COLS);

#pragma unroll 2
    for (int k = 0; k < CIN; k += 2) {
        // prefetch k+2, k+3 (clamped to row 0 at the tail; value unused)
        const int kp = (k + 2 < CIN) ? k + 2 : 0;
        float n0[CPT], n1[CPT];
        load_w<CPT>(n0, wb + (size_t)kp * COLS);
        load_w<CPT>(n1, wb + (size_t)(kp + 1) * COLS);

        // compute k with w0
        {
            ull xp[4];
#pragma unroll
            for (int p = 0; p < 4; p++)
                xp[p] = *reinterpret_cast<const ull*>(xb + k * RP + 2 * p);
            ull wp[CPT];
#pragma unroll
            for (int j = 0; j < CPT; j++) wp[j] = pack2(w0[j]);
#pragma unroll
            for (int p = 0; p < 4; p++)
#pragma unroll
                for (int j = 0; j < CPT; j++)
                    acc[p][j] = ffma2(xp[p], wp[j], acc[p][j]);
        }
        // compute k+1 with w1
        {
            ull xp[4];
#pragma unroll
            for (int p = 0; p < 4; p++)
                xp[p] = *reinterpret_cast<const ull*>(xb + (k + 1) * RP + 2 * p);
            ull wp[CPT];
#pragma unroll
            for (int j = 0; j < CPT; j++) wp[j] = pack2(w1[j]);
#pragma unroll
            for (int p = 0; p < 4; p++)
#pragma unroll
                for (int j = 0; j < CPT; j++)
                    acc[p][j] = ffma2(xp[p], wp[j], acc[p][j]);
        }
#pragma unroll
        for (int j = 0; j < CPT; j++) { w0[j] = n0[j]; w1[j] = n1[j]; }
    }

#pragma unroll
    for (int j = 0; j < CPT; j++) {
        float bc = __ldg(bias + c0 + j);
#pragma unroll
        for (int p = 0; p < 4; p++) {
            float2 v = unpack2(acc[p][j]);
            v.x += bc; v.y += bc;
            if (ACT == 1) {
                v.x = v.x * (1.0f / (1.0f + __expf(-v.x)));
                v.y = v.y * (1.0f / (1.0f + __expf(-v.y)));
            } else if (ACT == 2) {
                v.x = tanhf(v.x);
                v.y = tanhf(v.y);
            }
            *reinterpret_cast<ull*>(Yt + (yoff + c0 + j) * RP + r0 + 2 * p) =
                repack(v.x, v.y);
        }
    }
}

__global__ void __launch_bounds__(256, 2) step_kernel(
    const float* __restrict__ cc, const float* __restrict__ hebb,
    const int* __restrict__ conn,
    const float* __restrict__ sw1, const float* __restrict__ sb1,
    const float* __restrict__ sw2, const float* __restrict__ sb2,
    const float* __restrict__ mw1, const float* __restrict__ mb1,
    const float* __restrict__ mw2, const float* __restrict__ mb2,
    const float* __restrict__ dw1, const float* __restrict__ db1,
    float* __restrict__ out, int t, int p) {
    extern __shared__ float sm[];
    float* A = sm;                     // 256*RP transposed (mod_in / scratch)
    float* B = A + 256 * RP;           // 256*RP (hidden / state_in / msg_in)
    float* C = B + 256 * RP;           // 256*RP (mod_out / hidden)
    float* wk = C + 256 * RP;          // ROWS*KK sigmoid(w_conn)
    float* idn = wk + ROWS * KK;       // NT*DID new identity
    float* dec = idn + NT * DID;       // ROWS decay
    int* idxs = (int*)(dec + ROWS);    // NT*KK neighbor indices

    const int tid = threadIdx.x;
    const int n0 = blockIdx.x * NT;

    // ---- Phase 0: indices + sigmoid(w_conn) + transposed mod_in fills ----
    {
        int ln = tid >> 5, k = tid & 31;
        idxs[tid] = conn[(n0 + ln) * KK + k];
    }
    for (int i = tid; i < ROWS * KK; i += 256) {
        int r = i >> 5, k = i & 31, ln = r >> 2, b = r & 3;
        wk[i] = sigf(g_wc[((size_t)b * NN + n0 + ln) * KK + k]);
    }
    for (int i = tid; i < ROWS * KK; i += 256) {  // hebbian -> rows [0:32]
        int r = i >> 5, j = i & 31, ln = r >> 2, b = r & 3;
        A[j * RP + r] = hebb[((size_t)b * NN + n0 + ln) * KK + j];
    }
    for (int i = tid; i < ROWS * DD; i += 256) {  // h -> [32:96]
        int r = i >> 6, d = i & 63, ln = r >> 2, b = r & 3;
        A[(32 + d) * RP + r] = g_h[((size_t)b * NN + n0 + ln) * DD + d];
    }
    for (int i = tid; i < ROWS * DID; i += 256) {  // ident -> [96:128]
        int r = i >> 5, j = i & 31, ln = r >> 2;
        A[(96 + j) * RP + r] = g_ident[(n0 + ln) * DID + j];
    }
    for (int i = tid; i < ROWS * DD; i += 256) {  // inject -> [192:256]
        int r = i >> 6, d = i & 63, ln = r >> 2, b = r & 3;
        int n = n0 + ln;
        A[(192 + d) * RP + r] = cc[((size_t)b * TT + t) * DSCAN + (n >> 9) * DD + d];
    }
    __syncthreads();

    // ---- received = sum_k sigmoid(w) * msgs[neighbor] -> rows [128:192] ----
    {
        const int sub = tid >> 6;  // batch index
        const int d = tid & 63;
        const float* mp = g_msgs[p];
        for (int it = 0; it < NT; it++) {
            int r = it * 4 + sub;
            float acc = 0.0f;
#pragma unroll 8
            for (int k = 0; k < KK; k++) {
                int nb = idxs[it * KK + k];
                acc = fmaf(wk[r * KK + k], mp[((size_t)sub * NN + nb) * DD + d], acc);
            }
            A[(128 + d) * RP + r] = acc;
        }
    }
    __syncthreads();

    // ---- mod MLP ----
    gemmT<4, 1, 256, 256>(A, dw1, db1, B, 0);
    __syncthreads();
    gemmT<2, 0, 256, 128>(B, g_dw2p, g_db2p, C, 0);
    __syncthreads();

    // ---- w_new, decay, identity update (batch mean) ----
    for (int i = tid; i < ROWS * KK; i += 256) {
        int r = i >> 5, k = i & 31, ln = r >> 2, b = r & 3;
        g_wc[((size_t)b * NN + n0 + ln) * KK + k] = C[k * RP + r];
    }
    if (tid < ROWS) dec[tid] = sigf(C[32 * RP + tid]);
    {
        int ln = tid >> 5, j = tid & 31;
        const float* cr = C + (33 + j) * RP + ln * 4;
        float v = g_ident[(n0 + ln) * DID + j] +
                  0.25f * (cr[0] + cr[1] + cr[2] + cr[3]);
        idn[tid] = v;
        g_ident[(n0 + ln) * DID + j] = v;
    }
    __syncthreads();

    // ---- build state_in rows: [received, inject, h, ide2] into B ----
    for (int i = tid; i < 224 * 16; i += 256) {  // float2 over r
        int c = i >> 4, m = i & 15;
        int src;
        if (c < 64) src = 128 + c;
        else if (c < 128) src = 192 + (c - 64);
        else if (c < 192) src = 32 + (c - 128);
        else src = -1;
        float2 v;
        if (src >= 0) {
            v = *reinterpret_cast<const float2*>(A + src * RP + 2 * m);
        } else {
            int j = c - 192;
            int r = 2 * m;
            v.x = idn[(r >> 2) * DID + j];
            v.y = idn[((r + 1) >> 2) * DID + j];
        }
        *reinterpret_cast<float2*>(B + c * RP + 2 * m) = v;
    }
    __syncthreads();

    // ---- state MLP ----
    gemmT<4, 1, 224, 256>(B, sw1, sb1, C, 0);
    __syncthreads();
    gemmT<1, 2, 256, 64>(C, sw2, sb2, A, 96);  // tanh -> A rows [96:160]
    __syncthreads();

    // ---- h_new = decay*h + (1-decay)*tanh; write out + msg input ----
    for (int i = tid; i < ROWS * DD; i += 256) {
        int r = i >> 6, d = i & 63, ln = r >> 2, b = r & 3;
        float de = dec[r];
        float hn = de * A[(32 + d) * RP + r] + (1.0f - de) * A[(96 + d) * RP + r];
        g_h[((size_t)b * NN + n0 + ln) * DD + d] = hn;
        out[(((size_t)b * TT + t) * NN + n0 + ln) * DD + d] = hn;
        B[d * RP + r] = hn;
    }
    for (int i = tid; i < ROWS * DID; i += 256) {
        int r = i >> 5, j = i & 31;
        B[(64 + j) * RP + r] = idn[(r >> 2) * DID + j];
    }
    __syncthreads();

    // ---- msg MLP ----
    gemmT<4, 1, 96, 256>(B, mw1, mb1, C, 0);
    __syncthreads();
    gemmT<1, 2, 256, 64>(C, mw2, mb2, A, 0);  // tanh -> A rows [0:64]
    __syncthreads();
    for (int i = tid; i < ROWS * DD; i += 256) {
        int r = i >> 6, d = i & 63, ln = r >> 2, b = r & 3;
        g_msgs[p ^ 1][((size_t)b * NN + n0 + ln) * DD + d] = A[d * RP + r];
    }
}

__global__ void init_kernel(const float* __restrict__ h0, const float* __restrict__ m0,
                            const float* __restrict__ w0, const float* __restrict__ id0,
                            const float* __restrict__ dw2, const float* __restrict__ db2) {
    size_t i = (size_t)blockIdx.x * blockDim.x + threadIdx.x;
    if (i < (size_t)BSZ * NN * DD) {
        g_h[i] = h0[i];
        g_msgs[0][i] = m0[i];
    }
    if (i < (size_t)BSZ * NN * KK) g_wc[i] = w0[i];
    if (i < (size_t)NN * DID) g_ident[i] = id0[i];
    if (i < 256 * 128) {
        int r = (int)i >> 7, c = (int)i & 127;
        g_dw2p[i] = (c < 65) ? dw2[r * 65 + c] : 0.0f;
    }
    if (i < 128) g_db2p[i] = (i < 65) ? db2[i] : 0.0f;
}

#define SMEM_BYTES ((3 * 256 * RP + ROWS * KK + NT * DID + ROWS) * 4 + NT * KK * 4)

extern "C" void kernel_launch(void* const* d_in, const int* in_sizes, int n_in,
                              void* d_out, int out_size) {
    const float* cc   = (const float*)d_in[0];
    const float* h0   = (const float*)d_in[1];
    const float* m0   = (const float*)d_in[2];
    const float* w0   = (const float*)d_in[3];
    const float* hebb = (const float*)d_in[4];
    const float* id0  = (const float*)d_in[5];
    const float* sw1  = (const float*)d_in[6];
    const float* sb1  = (const float*)d_in[7];
    const float* sw2  = (const float*)d_in[8];
    const float* sb2  = (const float*)d_in[9];
    const float* mw1  = (const float*)d_in[10];
    const float* mb1  = (const float*)d_in[11];
    const float* mw2  = (const float*)d_in[12];
    const float* mb2  = (const float*)d_in[13];
    const float* dw1  = (const float*)d_in[14];
    const float* db1  = (const float*)d_in[15];
    const float* dw2  = (const float*)d_in[16];
    const float* db2  = (const float*)d_in[17];
    const int* conn   = (const int*)d_in[18];
    float* out = (float*)d_out;

    cudaFuncSetAttribute(step_kernel, cudaFuncAttributeMaxDynamicSharedMemorySize,
                         SMEM_BYTES);

    init_kernel<<<(BSZ * NN * DD + 255) / 256, 256>>>(h0, m0, w0, id0, dw2, db2);
    for (int t = 0; t < TT; t++) {
        step_kernel<<<NN / NT, 256, SMEM_BYTES>>>(
            cc, hebb, conn, sw1, sb1, sw2, sb2, mw1, mb1, mw2, mb2,
            dw1, db1, out, t, t & 1);
    }
}

// round 6
// speedup vs baseline: 1.2164x; 1.2164x over previous
#include <cuda_runtime.h>
#include <math.h>

#define NN 8192
#define KK 32
#define DD 64
#define DID 32
#define BSZ 4
#define TT 8
#define DSCAN 1024

#define NT 8            // nodes per block
#define ROWS 32         // NT * BSZ rows per block
#define RP 34           // transposed-buffer row pitch (even, conflict-spread)

typedef unsigned long long ull;

// Persistent state (allocation-free scratch)
__device__ float g_h[BSZ * NN * DD];
__device__ float g_msgs[2][BSZ * NN * DD];
__device__ float g_wc[BSZ * NN * KK];
__device__ float g_ident[NN * DID];
__device__ float g_dw2p[256 * 128];   // dw2 padded 65 -> 128 cols
__device__ float g_db2p[128];

__device__ __forceinline__ float sigf(float x) { return 1.0f / (1.0f + __expf(-x)); }

__device__ __forceinline__ ull ffma2(ull a, ull b, ull c) {
    ull d;
    asm("fma.rn.f32x2 %0, %1, %2, %3;" : "=l"(d) : "l"(a), "l"(b), "l"(c));
    return d;
}
__device__ __forceinline__ ull pack2(float x) {
    ull p;
    unsigned u = __float_as_uint(x);
    asm("mov.b64 %0, {%1, %2};" : "=l"(p) : "r"(u), "r"(u));
    return p;
}
__device__ __forceinline__ float2 unpack2(ull p) {
    unsigned lo, hi;
    asm("mov.b64 {%0, %1}, %2;" : "=r"(lo), "=r"(hi) : "l"(p));
    return make_float2(__uint_as_float(lo), __uint_as_float(hi));
}
__device__ __forceinline__ ull repack(float x, float y) {
    ull p;
    unsigned a = __float_as_uint(x), b = __float_as_uint(y);
    asm("mov.b64 %0, {%1, %2};" : "=l"(p) : "r"(a), "r"(b));
    return p;
}

// Yt[yoff+c][r] = act(sum_k Xt[k][r] * W[k][c] + b[c]).
// Xt transposed in smem (pitch RP). W plain row-major [CIN x COLS].
// 8 warps split COLS; lane = 4 row-groups x 8 col-groups; rows packed in f32x2.
// W loaded dense (LDG.128/64/32), splatted to {w,w} via ALU mov.b64.
// ACT: 0 = none, 1 = silu, 2 = tanh
template <int CPT, int ACT, int CIN, int COLS, int UNR>
__device__ __forceinline__ void gemmT(const float* Xt,
                                      const float* __restrict__ W,
                                      const float* __restrict__ bias,
                                      float* Yt, int yoff) {
    const int w = threadIdx.x >> 5;
    const int lane = threadIdx.x & 31;
    const int r0 = (lane >> 3) * 8;
    const int c0 = w * (COLS / 8) + (lane & 7) * CPT;
    ull acc[4][CPT];
#pragma unroll
    for (int p = 0; p < 4; p++)
#pragma unroll
        for (int j = 0; j < CPT; j++) acc[p][j] = 0ull;

    const float* xb = Xt + r0;
    const float* wb = W + c0;
#pragma unroll UNR
    for (int k = 0; k < CIN; k++) {
        ull xp[4];
#pragma unroll
        for (int p = 0; p < 4; p++)
            xp[p] = *reinterpret_cast<const ull*>(xb + k * RP + 2 * p);
        float wv[CPT];
        const float* wr = wb + (size_t)k * COLS;
        if (CPT == 4) {
            float4 f = __ldg(reinterpret_cast<const float4*>(wr));
            wv[0] = f.x; wv[1] = f.y; wv[2] = f.z; wv[3] = f.w;
        } else if (CPT == 2) {
            float2 f = __ldg(reinterpret_cast<const float2*>(wr));
            wv[0] = f.x; wv[1] = f.y;
        } else {
            wv[0] = __ldg(wr);
        }
        ull wp[CPT];
#pragma unroll
        for (int j = 0; j < CPT; j++) wp[j] = pack2(wv[j]);
#pragma unroll
        for (int p = 0; p < 4; p++)
#pragma unroll
            for (int j = 0; j < CPT; j++)
                acc[p][j] = ffma2(xp[p], wp[j], acc[p][j]);
    }
#pragma unroll
    for (int j = 0; j < CPT; j++) {
        float bc = __ldg(bias + c0 + j);
#pragma unroll
        for (int p = 0; p < 4; p++) {
            float2 v = unpack2(acc[p][j]);
            v.x += bc; v.y += bc;
            if (ACT == 1) {
                v.x = v.x * (1.0f / (1.0f + __expf(-v.x)));
                v.y = v.y * (1.0f / (1.0f + __expf(-v.y)));
            } else if (ACT == 2) {
                v.x = tanhf(v.x);
                v.y = tanhf(v.y);
            }
            *reinterpret_cast<ull*>(Yt + (yoff + c0 + j) * RP + r0 + 2 * p) =
                repack(v.x, v.y);
        }
    }
}

__global__ void __launch_bounds__(256, 2) step_kernel(
    const float* __restrict__ cc, const float* __restrict__ hebb,
    const int* __restrict__ conn,
    const float* __restrict__ sw1, const float* __restrict__ sb1,
    const float* __restrict__ sw2, const float* __restrict__ sb2,
    const float* __restrict__ mw1, const float* __restrict__ mb1,
    const float* __restrict__ mw2, const float* __restrict__ mb2,
    const float* __restrict__ dw1, const float* __restrict__ db1,
    float* __restrict__ out, int t, int p) {
    extern __shared__ float sm[];
    float* A = sm;                     // 256*RP transposed (mod_in / scratch)
    float* B = A + 256 * RP;           // 256*RP (hidden / state_in / msg_in)
    float* C = B + 256 * RP;           // 256*RP (mod_out / hidden)
    float* wk = C + 256 * RP;          // ROWS*KK sigmoid(w_conn)
    float* idn = wk + ROWS * KK;       // NT*DID new identity
    float* dec = idn + NT * DID;       // ROWS decay
    int* idxs = (int*)(dec + ROWS);    // NT*KK neighbor indices

    const int tid = threadIdx.x;
    const int n0 = blockIdx.x * NT;

    // ---- Phase 0: indices + sigmoid(w_conn) + transposed mod_in fills ----
    {
        int ln = tid >> 5, k = tid & 31;
        idxs[tid] = conn[(n0 + ln) * KK + k];
    }
    for (int i = tid; i < ROWS * KK; i += 256) {
        int r = i >> 5, k = i & 31, ln = r >> 2, b = r & 3;
        wk[i] = sigf(g_wc[((size_t)b * NN + n0 + ln) * KK + k]);
    }
    for (int i = tid; i < ROWS * KK; i += 256) {  // hebbian -> rows [0:32]
        int r = i >> 5, j = i & 31, ln = r >> 2, b = r & 3;
        A[j * RP + r] = hebb[((size_t)b * NN + n0 + ln) * KK + j];
    }
    for (int i = tid; i < ROWS * DD; i += 256) {  // h -> [32:96]
        int r = i >> 6, d = i & 63, ln = r >> 2, b = r & 3;
        A[(32 + d) * RP + r] = g_h[((size_t)b * NN + n0 + ln) * DD + d];
    }
    for (int i = tid; i < ROWS * DID; i += 256) {  // ident -> [96:128]
        int r = i >> 5, j = i & 31, ln = r >> 2;
        A[(96 + j) * RP + r] = g_ident[(n0 + ln) * DID + j];
    }
    for (int i = tid; i < ROWS * DD; i += 256) {  // inject -> [192:256]
        int r = i >> 6, d = i & 63, ln = r >> 2, b = r & 3;
        int n = n0 + ln;
        A[(192 + d) * RP + r] = cc[((size_t)b * TT + t) * DSCAN + (n >> 9) * DD + d];
    }
    __syncthreads();

    // ---- received = sum_k sigmoid(w) * msgs[neighbor] -> rows [128:192] ----
    // 512 tasks = (row r, d-quad q); each task: 32 k-iters with LDG.128
    {
        const float* mp = g_msgs[p];
#pragma unroll
        for (int task = tid; task < 512; task += 256) {
            int r = task >> 4;       // 0..31
            int q = task & 15;       // 0..15 (d-quad)
            int ln = r >> 2, b = r & 3;
            const float* wrow = wk + r * KK;
            const int* irow = idxs + ln * KK;
            const float* mb = mp + (size_t)b * NN * DD + 4 * q;
            float4 acc = make_float4(0.f, 0.f, 0.f, 0.f);
#pragma unroll 8
            for (int k = 0; k < KK; k++) {
                float wv = wrow[k];
                int nb = irow[k];
                float4 m = *reinterpret_cast<const float4*>(mb + (size_t)nb * DD);
                acc.x = fmaf(wv, m.x, acc.x);
                acc.y = fmaf(wv, m.y, acc.y);
                acc.z = fmaf(wv, m.z, acc.z);
                acc.w = fmaf(wv, m.w, acc.w);
            }
            float* dst = A + (128 + 4 * q) * RP + r;
            dst[0] = acc.x;
            dst[RP] = acc.y;
            dst[2 * RP] = acc.z;
            dst[3 * RP] = acc.w;
        }
    }
    __syncthreads();

    // ---- mod MLP ----
    gemmT<4, 1, 256, 256, 4>(A, dw1, db1, B, 0);
    __syncthreads();
    gemmT<2, 0, 256, 128, 8>(B, g_dw2p, g_db2p, C, 0);
    __syncthreads();

    // ---- w_new, decay, identity update (batch mean) ----
    for (int i = tid; i < ROWS * KK; i += 256) {
        int r = i >> 5, k = i & 31, ln = r >> 2, b = r & 3;
        g_wc[((size_t)b * NN + n0 + ln) * KK + k] = C[k * RP + r];
    }
    if (tid < ROWS) dec[tid] = sigf(C[32 * RP + tid]);
    {
        int ln = tid >> 5, j = tid & 31;
        const float* cr = C + (33 + j) * RP + ln * 4;
        float v = g_ident[(n0 + ln) * DID + j] +
                  0.25f * (cr[0] + cr[1] + cr[2] + cr[3]);
        idn[tid] = v;
        g_ident[(n0 + ln) * DID + j] = v;
    }
    __syncthreads();

    // ---- build state_in rows: [received, inject, h, ide2] into B ----
    for (int i = tid; i < 224 * 16; i += 256) {  // float2 over r
        int c = i >> 4, m = i & 15;
        int src;
        if (c < 64) src = 128 + c;
        else if (c < 128) src = 192 + (c - 64);
        else if (c < 192) src = 32 + (c - 128);
        else src = -1;
        float2 v;
        if (src >= 0) {
            v = *reinterpret_cast<const float2*>(A + src * RP + 2 * m);
        } else {
            int j = c - 192;
            int r = 2 * m;
            v.x = idn[(r >> 2) * DID + j];
            v.y = idn[((r + 1) >> 2) * DID + j];
        }
        *reinterpret_cast<float2*>(B + c * RP + 2 * m) = v;
    }
    __syncthreads();

    // ---- state MLP ----
    gemmT<4, 1, 224, 256, 4>(B, sw1, sb1, C, 0);
    __syncthreads();
    gemmT<1, 2, 256, 64, 8>(C, sw2, sb2, A, 96);  // tanh -> A rows [96:160]
    __syncthreads();

    // ---- h_new = decay*h + (1-decay)*tanh; write out + msg input ----
    for (int i = tid; i < ROWS * DD; i += 256) {
        int r = i >> 6, d = i & 63, ln = r >> 2, b = r & 3;
        float de = dec[r];
        float hn = de * A[(32 + d) * RP + r] + (1.0f - de) * A[(96 + d) * RP + r];
        g_h[((size_t)b * NN + n0 + ln) * DD + d] = hn;
        out[(((size_t)b * TT + t) * NN + n0 + ln) * DD + d] = hn;
        B[d * RP + r] = hn;
    }
    for (int i = tid; i < ROWS * DID; i += 256) {
        int r = i >> 5, j = i & 31;
        B[(64 + j) * RP + r] = idn[(r >> 2) * DID + j];
    }
    __syncthreads();

    // ---- msg MLP ----
    gemmT<4, 1, 96, 256, 4>(B, mw1, mb1, C, 0);
    __syncthreads();
    gemmT<1, 2, 256, 64, 8>(C, mw2, mb2, A, 0);  // tanh -> A rows [0:64]
    __syncthreads();
    for (int i = tid; i < ROWS * DD; i += 256) {
        int r = i >> 6, d = i & 63, ln = r >> 2, b = r & 3;
        g_msgs[p ^ 1][((size_t)b * NN + n0 + ln) * DD + d] = A[d * RP + r];
    }
}

__global__ void init_kernel(const float* __restrict__ h0, const float* __restrict__ m0,
                            const float* __restrict__ w0, const float* __restrict__ id0,
                            const float* __restrict__ dw2, const float* __restrict__ db2) {
    size_t i = (size_t)blockIdx.x * blockDim.x + threadIdx.x;
    if (i < (size_t)BSZ * NN * DD) {
        g_h[i] = h0[i];
        g_msgs[0][i] = m0[i];
    }
    if (i < (size_t)BSZ * NN * KK) g_wc[i] = w0[i];
    if (i < (size_t)NN * DID) g_ident[i] = id0[i];
    if (i < 256 * 128) {
        int r = (int)i >> 7, c = (int)i & 127;
        g_dw2p[i] = (c < 65) ? dw2[r * 65 + c] : 0.0f;
    }
    if (i < 128) g_db2p[i] = (i < 65) ? db2[i] : 0.0f;
}

#define SMEM_BYTES ((3 * 256 * RP + ROWS * KK + NT * DID + ROWS) * 4 + NT * KK * 4)

extern "C" void kernel_launch(void* const* d_in, const int* in_sizes, int n_in,
                              void* d_out, int out_size) {
    const float* cc   = (const float*)d_in[0];
    const float* h0   = (const float*)d_in[1];
    const float* m0   = (const float*)d_in[2];
    const float* w0   = (const float*)d_in[3];
    const float* hebb = (const float*)d_in[4];
    const float* id0  = (const float*)d_in[5];
    const float* sw1  = (const float*)d_in[6];
    const float* sb1  = (const float*)d_in[7];
    const float* sw2  = (const float*)d_in[8];
    const float* sb2  = (const float*)d_in[9];
    const float* mw1  = (const float*)d_in[10];
    const float* mb1  = (const float*)d_in[11];
    const float* mw2  = (const float*)d_in[12];
    const float* mb2  = (const float*)d_in[13];
    const float* dw1  = (const float*)d_in[14];
    const float* db1  = (const float*)d_in[15];
    const float* dw2  = (const float*)d_in[16];
    const float* db2  = (const float*)d_in[17];
    const int* conn   = (const int*)d_in[18];
    float* out = (float*)d_out;

    cudaFuncSetAttribute(step_kernel, cudaFuncAttributeMaxDynamicSharedMemorySize,
                         SMEM_BYTES);

    init_kernel<<<(BSZ * NN * DD + 255) / 256, 256>>>(h0, m0, w0, id0, dw2, db2);
    for (int t = 0; t < TT; t++) {
        step_kernel<<<NN / NT, 256, SMEM_BYTES>>>(
            cc, hebb, conn, sw1, sb1, sw2, sb2, mw1, mb1, mw2, mb2,
            dw1, db1, out, t, t & 1);
    }
}

// round 7
// speedup vs baseline: 1.2558x; 1.0323x over previous
#include <cuda_runtime.h>
#include <math.h>

#define NN 8192
#define KK 32
#define DD 64
#define DID 32
#define BSZ 4
#define TT 8
#define DSCAN 1024

#define NT 8            // nodes per block
#define ROWS 32         // NT * BSZ rows per block
#define RP 36           // transposed-buffer row pitch (16B-aligned k-rows)

typedef unsigned long long ull;

// Persistent state (allocation-free scratch)
__device__ float g_h[BSZ * NN * DD];
__device__ float g_msgs[2][BSZ * NN * DD];
__device__ float g_wc[BSZ * NN * KK];
__device__ float g_ident[NN * DID];
__device__ float g_dw2p[256 * 128];   // dw2 padded 65 -> 128 cols
__device__ float g_db2p[128];

__device__ __forceinline__ float sigf(float x) { return 1.0f / (1.0f + __expf(-x)); }

__device__ __forceinline__ ull ffma2(ull a, ull b, ull c) {
    ull d;
    asm("fma.rn.f32x2 %0, %1, %2, %3;" : "=l"(d) : "l"(a), "l"(b), "l"(c));
    return d;
}
__device__ __forceinline__ ull pack2(float x) {
    ull p;
    unsigned u = __float_as_uint(x);
    asm("mov.b64 %0, {%1, %2};" : "=l"(p) : "r"(u), "r"(u));
    return p;
}
__device__ __forceinline__ float2 unpack2(ull p) {
    unsigned lo, hi;
    asm("mov.b64 {%0, %1}, %2;" : "=r"(lo), "=r"(hi) : "l"(p));
    return make_float2(__uint_as_float(lo), __uint_as_float(hi));
}
__device__ __forceinline__ ull repack(float x, float y) {
    ull p;
    unsigned a = __float_as_uint(x), b = __float_as_uint(y);
    asm("mov.b64 %0, {%1, %2};" : "=l"(p) : "r"(a), "r"(b));
    return p;
}

// One contiguous k-segment of the GEMM: LEN rows of X starting at xs, weights ws.
template <int CPT, int LEN, int COLS, int UNR>
__device__ __forceinline__ void gemm_seg(const float* xs, const float* __restrict__ ws,
                                         ull (&acc)[4][CPT]) {
#pragma unroll UNR
    for (int i = 0; i < LEN; i++) {
        ulonglong2 xq0 = *reinterpret_cast<const ulonglong2*>(xs + i * RP);
        ulonglong2 xq1 = *reinterpret_cast<const ulonglong2*>(xs + i * RP + 4);
        ull xp[4] = {xq0.x, xq0.y, xq1.x, xq1.y};
        float wv[CPT];
        const float* wr = ws + (size_t)i * COLS;
        if (CPT == 4) {
            float4 f = __ldg(reinterpret_cast<const float4*>(wr));
            wv[0] = f.x; wv[1] = f.y; wv[2] = f.z; wv[3] = f.w;
        } else if (CPT == 2) {
            float2 f = __ldg(reinterpret_cast<const float2*>(wr));
            wv[0] = f.x; wv[1] = f.y;
        } else {
            wv[0] = __ldg(wr);
        }
        ull wp[CPT];
#pragma unroll
        for (int j = 0; j < CPT; j++) wp[j] = pack2(wv[j]);
#pragma unroll
        for (int p = 0; p < 4; p++)
#pragma unroll
            for (int j = 0; j < CPT; j++)
                acc[p][j] = ffma2(xp[p], wp[j], acc[p][j]);
    }
}

// Segmented GEMM: input rows are up to 4 compile-time (base,len) segments of Xt.
// 8 warps split COLS; lane = 4 row-groups x 8 col-groups; rows packed in f32x2.
// WSYNC: barrier between accumulation and writeback (for in-place output).
template <int CPT, int ACT, int COLS, int UNR, bool WSYNC,
          int B0, int L0, int B1, int L1, int B2, int L2, int B3, int L3>
__device__ __forceinline__ void gemmS(const float* Xt, const float* __restrict__ W,
                                      const float* __restrict__ bias,
                                      float* Yt, int yoff) {
    const int w = threadIdx.x >> 5;
    const int lane = threadIdx.x & 31;
    const int r0 = (lane >> 3) * 8;
    const int c0 = w * (COLS / 8) + (lane & 7) * CPT;
    ull acc[4][CPT];
#pragma unroll
    for (int p = 0; p < 4; p++)
#pragma unroll
        for (int j = 0; j < CPT; j++) acc[p][j] = 0ull;

    const float* xb = Xt + r0;
    const float* wb = W + c0;
    gemm_seg<CPT, L0, COLS, UNR>(xb + B0 * RP, wb, acc);
    if (L1 > 0) gemm_seg<CPT, L1, COLS, UNR>(xb + B1 * RP, wb + (size_t)L0 * COLS, acc);
    if (L2 > 0) gemm_seg<CPT, L2, COLS, UNR>(xb + B2 * RP, wb + (size_t)(L0 + L1) * COLS, acc);
    if (L3 > 0) gemm_seg<CPT, L3, COLS, UNR>(xb + B3 * RP, wb + (size_t)(L0 + L1 + L2) * COLS, acc);

    if (WSYNC) __syncthreads();

#pragma unroll
    for (int j = 0; j < CPT; j++) {
        float bc = __ldg(bias + c0 + j);
#pragma unroll
        for (int p = 0; p < 4; p++) {
            float2 v = unpack2(acc[p][j]);
            v.x += bc; v.y += bc;
            if (ACT == 1) {
                v.x = v.x * (1.0f / (1.0f + __expf(-v.x)));
                v.y = v.y * (1.0f / (1.0f + __expf(-v.y)));
            } else if (ACT == 2) {
                v.x = tanhf(v.x);
                v.y = tanhf(v.y);
            }
            *reinterpret_cast<ull*>(Yt + (yoff + c0 + j) * RP + r0 + 2 * p) =
                repack(v.x, v.y);
        }
    }
}

// msg layer 2: CPT=1, tanh, writes g_msgs directly from registers.
__device__ __forceinline__ void gemm_msg2(const float* Xt, const float* __restrict__ W,
                                          const float* __restrict__ bias,
                                          float* __restrict__ gm, int n0) {
    const int w = threadIdx.x >> 5;
    const int lane = threadIdx.x & 31;
    const int r0 = (lane >> 3) * 8;
    const int c0 = w * 8 + (lane & 7);
    ull acc[4][1];
#pragma unroll
    for (int p = 0; p < 4; p++) acc[p][0] = 0ull;
    gemm_seg<1, 256, 64, 8>(Xt + r0, W + c0, acc);
    float bc = __ldg(bias + c0);
#pragma unroll
    for (int p = 0; p < 4; p++) {
        float2 v = unpack2(acc[p][0]);
        v.x = tanhf(v.x + bc);
        v.y = tanhf(v.y + bc);
        int r = r0 + 2 * p;
        gm[((size_t)(r & 3) * NN + n0 + (r >> 2)) * DD + c0] = v.x;
        gm[((size_t)((r + 1) & 3) * NN + n0 + ((r + 1) >> 2)) * DD + c0] = v.y;
    }
}

__global__ void __launch_bounds__(256, 2) step_kernel(
    const float* __restrict__ cc, const float* __restrict__ hebb,
    const int* __restrict__ conn,
    const float* __restrict__ sw1, const float* __restrict__ sb1,
    const float* __restrict__ sw2, const float* __restrict__ sb2,
    const float* __restrict__ mw1, const float* __restrict__ mb1,
    const float* __restrict__ mw2, const float* __restrict__ mb2,
    const float* __restrict__ dw1, const float* __restrict__ db1,
    float* __restrict__ out, int t, int p) {
    extern __shared__ float sm[];
    float* A = sm;                     // 256*RP transposed activations
    float* B = A + 256 * RP;           // 256*RP hidden / layer-2 out (in-place)
    float* wk = B + 256 * RP;          // ROWS*KK sigmoid(w_conn)
    float* dec = wk + ROWS * KK;       // ROWS decay
    int* idxs = (int*)(dec + ROWS);    // NT*KK neighbor indices

    const int tid = threadIdx.x;
    const int n0 = blockIdx.x * NT;

    // ---- Phase 0: indices + sigmoid(w_conn) + transposed mod_in fills ----
    // A rows: [0:32] hebbian, [32:96] h, [96:128] ident, [128:192] received,
    //         [192:256] inject
    {
        int ln = tid >> 5, k = tid & 31;
        idxs[tid] = conn[(n0 + ln) * KK + k];
    }
    for (int i = tid; i < ROWS * KK; i += 256) {
        int r = i >> 5, k = i & 31, ln = r >> 2, b = r & 3;
        wk[i] = sigf(g_wc[((size_t)b * NN + n0 + ln) * KK + k]);
    }
    for (int i = tid; i < ROWS * KK; i += 256) {
        int r = i >> 5, j = i & 31, ln = r >> 2, b = r & 3;
        A[j * RP + r] = hebb[((size_t)b * NN + n0 + ln) * KK + j];
    }
    for (int i = tid; i < ROWS * DD; i += 256) {
        int r = i >> 6, d = i & 63, ln = r >> 2, b = r & 3;
        A[(32 + d) * RP + r] = g_h[((size_t)b * NN + n0 + ln) * DD + d];
    }
    for (int i = tid; i < ROWS * DID; i += 256) {
        int r = i >> 5, j = i & 31, ln = r >> 2;
        A[(96 + j) * RP + r] = g_ident[(n0 + ln) * DID + j];
    }
    for (int i = tid; i < ROWS * DD; i += 256) {
        int r = i >> 6, d = i & 63, ln = r >> 2, b = r & 3;
        int n = n0 + ln;
        A[(192 + d) * RP + r] = cc[((size_t)b * TT + t) * DSCAN + (n >> 9) * DD + d];
    }
    __syncthreads();

    // ---- received = sum_k sigmoid(w) * msgs[neighbor] -> rows [128:192] ----
    {
        const float* mp = g_msgs[p];
#pragma unroll
        for (int task = tid; task < 512; task += 256) {
            int r = task >> 4;
            int q = task & 15;
            int ln = r >> 2, b = r & 3;
            const float* wrow = wk + r * KK;
            const int* irow = idxs + ln * KK;
            const float* mb = mp + (size_t)b * NN * DD + 4 * q;
            float4 acc = make_float4(0.f, 0.f, 0.f, 0.f);
#pragma unroll 8
            for (int k = 0; k < KK; k++) {
                float wv = wrow[k];
                int nb = irow[k];
                float4 m = __ldcg(reinterpret_cast<const float4*>(mb + (size_t)nb * DD));
                acc.x = fmaf(wv, m.x, acc.x);
                acc.y = fmaf(wv, m.y, acc.y);
                acc.z = fmaf(wv, m.z, acc.z);
                acc.w = fmaf(wv, m.w, acc.w);
            }
            float* dst = A + (128 + 4 * q) * RP + r;
            dst[0] = acc.x;
            dst[RP] = acc.y;
            dst[2 * RP] = acc.z;
            dst[3 * RP] = acc.w;
        }
    }
    __syncthreads();

    // ---- mod MLP: layer1 A[0:256] -> B; layer2 B -> B[0:128] in-place ----
    gemmS<4, 1, 256, 4, false, 0, 256, 0, 0, 0, 0, 0, 0>(A, dw1, db1, B, 0);
    __syncthreads();
    gemmS<2, 0, 128, 8, true, 0, 256, 0, 0, 0, 0, 0, 0>(B, g_dw2p, g_db2p, B, 0);
    __syncthreads();

    // ---- w_new, decay, identity update; ide2 -> A rows [96:128] ----
    for (int i = tid; i < ROWS * KK; i += 256) {
        int r = i >> 5, k = i & 31, ln = r >> 2, b = r & 3;
        g_wc[((size_t)b * NN + n0 + ln) * KK + k] = B[k * RP + r];
    }
    if (tid < ROWS) dec[tid] = sigf(B[32 * RP + tid]);
    {
        int ln = tid >> 5, j = tid & 31;
        const float* cr = B + (33 + j) * RP + ln * 4;
        float v = g_ident[(n0 + ln) * DID + j] +
                  0.25f * (cr[0] + cr[1] + cr[2] + cr[3]);
        g_ident[(n0 + ln) * DID + j] = v;
        float* ar = A + (96 + j) * RP + ln * 4;
        ar[0] = v; ar[1] = v; ar[2] = v; ar[3] = v;
    }
    __syncthreads();

    // ---- state MLP: layer1 reads segments [received,inject,h,ide2] of A ----
    gemmS<4, 1, 256, 4, false, 128, 64, 192, 64, 32, 64, 96, 32>(A, sw1, sb1, B, 0);
    __syncthreads();
    gemmS<1, 2, 64, 8, false, 0, 256, 0, 0, 0, 0, 0, 0>(B, sw2, sb2, A, 128); // tanh -> A[128:192]
    __syncthreads();

    // ---- h_new = decay*h + (1-decay)*tanh -> A rows [192:256], g_h, out ----
    for (int i = tid; i < ROWS * DD; i += 256) {
        int r = i >> 6, d = i & 63, ln = r >> 2, b = r & 3;
        float de = dec[r];
        float hn = de * A[(32 + d) * RP + r] + (1.0f - de) * A[(128 + d) * RP + r];
        g_h[((size_t)b * NN + n0 + ln) * DD + d] = hn;
        out[(((size_t)b * TT + t) * NN + n0 + ln) * DD + d] = hn;
        A[(192 + d) * RP + r] = hn;
    }
    __syncthreads();

    // ---- msg MLP: layer1 reads [h_new, ide2]; layer2 writes g_msgs direct ----
    gemmS<4, 1, 256, 4, false, 192, 64, 96, 32, 0, 0, 0, 0>(A, mw1, mb1, B, 0);
    __syncthreads();
    gemm_msg2(B, mw2, mb2, g_msgs[p ^ 1], n0);
}

__global__ void init_kernel(const float* __restrict__ h0, const float* __restrict__ m0,
                            const float* __restrict__ w0, const float* __restrict__ id0,
                            const float* __restrict__ dw2, const float* __restrict__ db2) {
    size_t i = (size_t)blockIdx.x * blockDim.x + threadIdx.x;
    if (i < (size_t)BSZ * NN * DD) {
        g_h[i] = h0[i];
        g_msgs[0][i] = m0[i];
    }
    if (i < (size_t)BSZ * NN * KK) g_wc[i] = w0[i];
    if (i < (size_t)NN * DID) g_ident[i] = id0[i];
    if (i < 256 * 128) {
        int r = (int)i >> 7, c = (int)i & 127;
        g_dw2p[i] = (c < 65) ? dw2[r * 65 + c] : 0.0f;
    }
    if (i < 128) g_db2p[i] = (i < 65) ? db2[i] : 0.0f;
}

#define SMEM_BYTES ((2 * 256 * RP + ROWS * KK + ROWS) * 4 + NT * KK * 4)

extern "C" void kernel_launch(void* const* d_in, const int* in_sizes, int n_in,
                              void* d_out, int out_size) {
    const float* cc   = (const float*)d_in[0];
    const float* h0   = (const float*)d_in[1];
    const float* m0   = (const float*)d_in[2];
    const float* w0   = (const float*)d_in[3];
    const float* hebb = (const float*)d_in[4];
    const float* id0  = (const float*)d_in[5];
    const float* sw1  = (const float*)d_in[6];
    const float* sb1  = (const float*)d_in[7];
    const float* sw2  = (const float*)d_in[8];
    const float* sb2  = (const float*)d_in[9];
    const float* mw1  = (const float*)d_in[10];
    const float* mb1  = (const float*)d_in[11];
    const float* mw2  = (const float*)d_in[12];
    const float* mb2  = (const float*)d_in[13];
    const float* dw1  = (const float*)d_in[14];
    const float* db1  = (const float*)d_in[15];
    const float* dw2  = (const float*)d_in[16];
    const float* db2  = (const float*)d_in[17];
    const int* conn   = (const int*)d_in[18];
    float* out = (float*)d_out;

    cudaFuncSetAttribute(step_kernel, cudaFuncAttributeMaxDynamicSharedMemorySize,
                         SMEM_BYTES);

    init_kernel<<<(BSZ * NN * DD + 255) / 256, 256>>>(h0, m0, w0, id0, dw2, db2);
    for (int t = 0; t < TT; t++) {
        step_kernel<<<NN / NT, 256, SMEM_BYTES>>>(
            cc, hebb, conn, sw1, sb1, sw2, sb2, mw1, mb1, mw2, mb2,
            dw1, db1, out, t, t & 1);
    }
}

// round 8
// speedup vs baseline: 1.2653x; 1.0076x over previous
#include <cuda_runtime.h>
#include <math.h>

#define NN 8192
#define KK 32
#define DD 64
#define DID 32
#define BSZ 4
#define TT 8
#define DSCAN 1024

#define NT 8            // nodes per block
#define ROWS 32         // NT * BSZ rows per block
#define RPA 36          // A pitch (16B-aligned rows, conflict-spread)
#define RPB 32          // B pitch (swizzled rows)

typedef unsigned long long ull;

// Persistent state (allocation-free scratch)
__device__ float g_h[BSZ * NN * DD];
__device__ float g_msgs[2][BSZ * NN * DD];
__device__ float g_wc[BSZ * NN * KK];
__device__ float g_ident[NN * DID];
__device__ float g_dw2p[256 * 128];   // dw2 padded 65 -> 128 cols
__device__ float g_db2p[128];

__device__ __forceinline__ float sigf(float x) { return 1.0f / (1.0f + __expf(-x)); }

// B-buffer swizzled index: row-coordinate r XORed at 32B granularity by row.
__device__ __forceinline__ int bswz(int row) { return ((row >> 2) & 3) << 3; }
__device__ __forceinline__ int bidx(int row, int r) {
    return row * RPB + ((r & 24) ^ bswz(row)) + (r & 7);
}

__device__ __forceinline__ ull ffma2(ull a, ull b, ull c) {
    ull d;
    asm("fma.rn.f32x2 %0, %1, %2, %3;" : "=l"(d) : "l"(a), "l"(b), "l"(c));
    return d;
}
__device__ __forceinline__ ull pack2(float x) {
    ull p;
    unsigned u = __float_as_uint(x);
    asm("mov.b64 %0, {%1, %2};" : "=l"(p) : "r"(u), "r"(u));
    return p;
}
__device__ __forceinline__ float2 unpack2(ull p) {
    unsigned lo, hi;
    asm("mov.b64 {%0, %1}, %2;" : "=r"(lo), "=r"(hi) : "l"(p));
    return make_float2(__uint_as_float(lo), __uint_as_float(hi));
}
__device__ __forceinline__ ull repack(float x, float y) {
    ull p;
    unsigned a = __float_as_uint(x), b = __float_as_uint(y);
    asm("mov.b64 %0, {%1, %2};" : "=l"(p) : "r"(a), "r"(b));
    return p;
}

// One contiguous k-segment: LEN rows starting at buffer row `base`.
template <int CPT, int LEN, int COLS, int UNR, int PITCH, bool SWZ>
__device__ __forceinline__ void gemm_seg(const float* Xbuf, int base, int r0,
                                         const float* __restrict__ ws,
                                         ull (&acc)[4][CPT]) {
#pragma unroll UNR
    for (int i = 0; i < LEN; i++) {
        const int row = base + i;
        const int off = row * PITCH + (SWZ ? (r0 ^ bswz(row)) : r0);
        ulonglong2 xq0 = *reinterpret_cast<const ulonglong2*>(Xbuf + off);
        ulonglong2 xq1 = *reinterpret_cast<const ulonglong2*>(Xbuf + off + 4);
        ull xp[4] = {xq0.x, xq0.y, xq1.x, xq1.y};
        float wv[CPT];
        const float* wr = ws + (size_t)i * COLS;
        if (CPT == 4) {
            float4 f = __ldg(reinterpret_cast<const float4*>(wr));
            wv[0] = f.x; wv[1] = f.y; wv[2] = f.z; wv[3] = f.w;
        } else if (CPT == 2) {
            float2 f = __ldg(reinterpret_cast<const float2*>(wr));
            wv[0] = f.x; wv[1] = f.y;
        } else {
            wv[0] = __ldg(wr);
        }
        ull wp[CPT];
#pragma unroll
        for (int j = 0; j < CPT; j++) wp[j] = pack2(wv[j]);
#pragma unroll
        for (int p = 0; p < 4; p++)
#pragma unroll
            for (int j = 0; j < CPT; j++)
                acc[p][j] = ffma2(xp[p], wp[j], acc[p][j]);
    }
}

// Segmented GEMM over up to 4 compile-time (base,len) row segments.
// 8 warps split COLS; lane = 4 row-groups x 8 col-groups; rows packed f32x2.
template <int CPT, int ACT, int COLS, int UNR, bool WSYNC,
          int IPITCH, bool ISWZ, int OPITCH, bool OSWZ,
          int B0, int L0, int B1, int L1, int B2, int L2, int B3, int L3>
__device__ __forceinline__ void gemmS(const float* Xt, const float* __restrict__ W,
                                      const float* __restrict__ bias,
                                      float* Yt, int yoff) {
    const int w = threadIdx.x >> 5;
    const int lane = threadIdx.x & 31;
    const int r0 = (lane >> 3) * 8;
    const int c0 = w * (COLS / 8) + (lane & 7) * CPT;
    ull acc[4][CPT];
#pragma unroll
    for (int p = 0; p < 4; p++)
#pragma unroll
        for (int j = 0; j < CPT; j++) acc[p][j] = 0ull;

    const float* wb = W + c0;
    gemm_seg<CPT, L0, COLS, UNR, IPITCH, ISWZ>(Xt, B0, r0, wb, acc);
    if (L1 > 0) gemm_seg<CPT, L1, COLS, UNR, IPITCH, ISWZ>(Xt, B1, r0, wb + (size_t)L0 * COLS, acc);
    if (L2 > 0) gemm_seg<CPT, L2, COLS, UNR, IPITCH, ISWZ>(Xt, B2, r0, wb + (size_t)(L0 + L1) * COLS, acc);
    if (L3 > 0) gemm_seg<CPT, L3, COLS, UNR, IPITCH, ISWZ>(Xt, B3, r0, wb + (size_t)(L0 + L1 + L2) * COLS, acc);

    if (WSYNC) __syncthreads();

#pragma unroll
    for (int j = 0; j < CPT; j++) {
        float bc = __ldg(bias + c0 + j);
#pragma unroll
        for (int p = 0; p < 4; p++) {
            float2 v = unpack2(acc[p][j]);
            v.x += bc; v.y += bc;
            if (ACT == 1) {
                v.x = v.x * (1.0f / (1.0f + __expf(-v.x)));
                v.y = v.y * (1.0f / (1.0f + __expf(-v.y)));
            } else if (ACT == 2) {
                v.x = tanhf(v.x);
                v.y = tanhf(v.y);
            }
            const int row = yoff + c0 + j;
            const int ro = OSWZ ? (r0 ^ bswz(row)) : r0;
            *reinterpret_cast<ull*>(Yt + row * OPITCH + ro + 2 * p) = repack(v.x, v.y);
        }
    }
}

// msg layer 2: CPT=1, tanh, reads B (swizzled), writes g_msgs directly.
__device__ __forceinline__ void gemm_msg2(const float* Bt, const float* __restrict__ W,
                                          const float* __restrict__ bias,
                                          float* __restrict__ gm, int n0) {
    const int w = threadIdx.x >> 5;
    const int lane = threadIdx.x & 31;
    const int r0 = (lane >> 3) * 8;
    const int c0 = w * 8 + (lane & 7);
    ull acc[4][1];
#pragma unroll
    for (int p = 0; p < 4; p++) acc[p][0] = 0ull;
    gemm_seg<1, 256, 64, 8, RPB, true>(Bt, 0, r0, W + c0, acc);
    float bc = __ldg(bias + c0);
#pragma unroll
    for (int p = 0; p < 4; p++) {
        float2 v = unpack2(acc[p][0]);
        v.x = tanhf(v.x + bc);
        v.y = tanhf(v.y + bc);
        int r = r0 + 2 * p;
        gm[((size_t)(r & 3) * NN + n0 + (r >> 2)) * DD + c0] = v.x;
        gm[((size_t)((r + 1) & 3) * NN + n0 + ((r + 1) >> 2)) * DD + c0] = v.y;
    }
}

__global__ void __launch_bounds__(256, 3) step_kernel(
    const float* __restrict__ cc, const float* __restrict__ hebb,
    const int* __restrict__ conn,
    const float* __restrict__ sw1, const float* __restrict__ sb1,
    const float* __restrict__ sw2, const float* __restrict__ sb2,
    const float* __restrict__ mw1, const float* __restrict__ mb1,
    const float* __restrict__ mw2, const float* __restrict__ mb2,
    const float* __restrict__ dw1, const float* __restrict__ db1,
    float* __restrict__ out, int t, int p) {
    extern __shared__ float sm[];
    float* A = sm;                     // 256*RPA transposed activations
    float* B = A + 256 * RPA;          // 256*RPB hidden (swizzled rows)
    float* dec = B + 256 * RPB;        // ROWS decay
    // transient (dead after gather, overwritten by mod layer1 output):
    float* wk = B;                     // ROWS*KK sigmoid(w_conn)
    int* idxs = (int*)(B + ROWS * KK); // NT*KK neighbor indices

    const int tid = threadIdx.x;
    const int n0 = blockIdx.x * NT;

    // ---- Phase 0: indices + sigmoid(w_conn) + transposed mod_in fills ----
    // A rows: [0:32] hebbian, [32:96] h, [96:128] ident, [128:192] received,
    //         [192:256] inject
    {
        int ln = tid >> 5, k = tid & 31;
        idxs[tid] = conn[(n0 + ln) * KK + k];
    }
    for (int i = tid; i < ROWS * KK; i += 256) {
        int r = i >> 5, k = i & 31, ln = r >> 2, b = r & 3;
        wk[i] = sigf(g_wc[((size_t)b * NN + n0 + ln) * KK + k]);
    }
    for (int i = tid; i < ROWS * KK; i += 256) {
        int r = i >> 5, j = i & 31, ln = r >> 2, b = r & 3;
        A[j * RPA + r] = hebb[((size_t)b * NN + n0 + ln) * KK + j];
    }
    for (int i = tid; i < ROWS * DD; i += 256) {
        int r = i >> 6, d = i & 63, ln = r >> 2, b = r & 3;
        A[(32 + d) * RPA + r] = g_h[((size_t)b * NN + n0 + ln) * DD + d];
    }
    for (int i = tid; i < ROWS * DID; i += 256) {
        int r = i >> 5, j = i & 31, ln = r >> 2;
        A[(96 + j) * RPA + r] = g_ident[(n0 + ln) * DID + j];
    }
    for (int i = tid; i < ROWS * DD; i += 256) {
        int r = i >> 6, d = i & 63, ln = r >> 2, b = r & 3;
        int n = n0 + ln;
        A[(192 + d) * RPA + r] = cc[((size_t)b * TT + t) * DSCAN + (n >> 9) * DD + d];
    }
    __syncthreads();

    // ---- received = sum_k sigmoid(w) * msgs[neighbor] -> A rows [128:192] ----
    {
        const float* mp = g_msgs[p];
#pragma unroll
        for (int task = tid; task < 512; task += 256) {
            int r = task >> 4;
            int q = task & 15;
            int ln = r >> 2, b = r & 3;
            const float* wrow = wk + r * KK;
            const int* irow = idxs + ln * KK;
            const float* mb = mp + (size_t)b * NN * DD + 4 * q;
            float4 acc = make_float4(0.f, 0.f, 0.f, 0.f);
#pragma unroll 8
            for (int k = 0; k < KK; k++) {
                float wv = wrow[k];
                int nb = irow[k];
                float4 m = __ldcg(reinterpret_cast<const float4*>(mb + (size_t)nb * DD));
                acc.x = fmaf(wv, m.x, acc.x);
                acc.y = fmaf(wv, m.y, acc.y);
                acc.z = fmaf(wv, m.z, acc.z);
                acc.w = fmaf(wv, m.w, acc.w);
            }
            float* dst = A + (128 + 4 * q) * RPA + r;
            dst[0] = acc.x;
            dst[RPA] = acc.y;
            dst[2 * RPA] = acc.z;
            dst[3 * RPA] = acc.w;
        }
    }
    __syncthreads();

    // ---- mod MLP: layer1 A[0:256] -> B; layer2 B -> B[0:128] in-place ----
    gemmS<4, 1, 256, 4, false, RPA, false, RPB, true,
          0, 256, 0, 0, 0, 0, 0, 0>(A, dw1, db1, B, 0);
    __syncthreads();
    gemmS<2, 0, 128, 8, true, RPB, true, RPB, true,
          0, 256, 0, 0, 0, 0, 0, 0>(B, g_dw2p, g_db2p, B, 0);
    __syncthreads();

    // ---- w_new, decay, identity update; ide2 -> A rows [96:128] ----
    for (int i = tid; i < ROWS * KK; i += 256) {
        int r = i >> 5, k = i & 31, ln = r >> 2, b = r & 3;
        g_wc[((size_t)b * NN + n0 + ln) * KK + k] = B[bidx(k, r)];
    }
    if (tid < ROWS) dec[tid] = sigf(B[bidx(32, tid)]);
    {
        int ln = tid >> 5, j = tid & 31;
        int row = 33 + j;
        float v = g_ident[(n0 + ln) * DID + j] +
                  0.25f * (B[bidx(row, ln * 4 + 0)] + B[bidx(row, ln * 4 + 1)] +
                           B[bidx(row, ln * 4 + 2)] + B[bidx(row, ln * 4 + 3)]);
        g_ident[(n0 + ln) * DID + j] = v;
        float* ar = A + (96 + j) * RPA + ln * 4;
        ar[0] = v; ar[1] = v; ar[2] = v; ar[3] = v;
    }
    __syncthreads();

    // ---- state MLP: layer1 reads segments [received,inject,h,ide2] of A ----
    gemmS<4, 1, 256, 4, false, RPA, false, RPB, true,
          128, 64, 192, 64, 32, 64, 96, 32>(A, sw1, sb1, B, 0);
    __syncthreads();
    gemmS<1, 2, 64, 8, false, RPB, true, RPA, false,
          0, 256, 0, 0, 0, 0, 0, 0>(B, sw2, sb2, A, 128);  // tanh -> A[128:192]
    __syncthreads();

    // ---- h_new = decay*h + (1-decay)*tanh -> A rows [192:256], g_h, out ----
    for (int i = tid; i < ROWS * DD; i += 256) {
        int r = i >> 6, d = i & 63, ln = r >> 2, b = r & 3;
        float de = dec[r];
        float hn = de * A[(32 + d) * RPA + r] + (1.0f - de) * A[(128 + d) * RPA + r];
        g_h[((size_t)b * NN + n0 + ln) * DD + d] = hn;
        out[(((size_t)b * TT + t) * NN + n0 + ln) * DD + d] = hn;
        A[(192 + d) * RPA + r] = hn;
    }
    __syncthreads();

    // ---- msg MLP: layer1 reads [h_new, ide2]; layer2 writes g_msgs direct ----
    gemmS<4, 1, 256, 4, false, RPA, false, RPB, true,
          192, 64, 96, 32, 0, 0, 0, 0>(A, mw1, mb1, B, 0);
    __syncthreads();
    gemm_msg2(B, mw2, mb2, g_msgs[p ^ 1], n0);
}

__global__ void init_kernel(const float* __restrict__ h0, const float* __restrict__ m0,
                            const float* __restrict__ w0, const float* __restrict__ id0,
                            const float* __restrict__ dw2, const float* __restrict__ db2) {
    size_t i = (size_t)blockIdx.x * blockDim.x + threadIdx.x;
    if (i < (size_t)BSZ * NN * DD) {
        g_h[i] = h0[i];
        g_msgs[0][i] = m0[i];
    }
    if (i < (size_t)BSZ * NN * KK) g_wc[i] = w0[i];
    if (i < (size_t)NN * DID) g_ident[i] = id0[i];
    if (i < 256 * 128) {
        int r = (int)i >> 7, c = (int)i & 127;
        g_dw2p[i] = (c < 65) ? dw2[r * 65 + c] : 0.0f;
    }
    if (i < 128) g_db2p[i] = (i < 65) ? db2[i] : 0.0f;
}

#define SMEM_BYTES ((256 * RPA + 256 * RPB + ROWS) * 4)

extern "C" void kernel_launch(void* const* d_in, const int* in_sizes, int n_in,
                              void* d_out, int out_size) {
    const float* cc   = (const float*)d_in[0];
    const float* h0   = (const float*)d_in[1];
    const float* m0   = (const float*)d_in[2];
    const float* w0   = (const float*)d_in[3];
    const float* hebb = (const float*)d_in[4];
    const float* id0  = (const float*)d_in[5];
    const float* sw1  = (const float*)d_in[6];
    const float* sb1  = (const float*)d_in[7];
    const float* sw2  = (const float*)d_in[8];
    const float* sb2  = (const float*)d_in[9];
    const float* mw1  = (const float*)d_in[10];
    const float* mb1  = (const float*)d_in[11];
    const float* mw2  = (const float*)d_in[12];
    const float* mb2  = (const float*)d_in[13];
    const float* dw1  = (const float*)d_in[14];
    const float* db1  = (const float*)d_in[15];
    const float* dw2  = (const float*)d_in[16];
    const float* db2  = (const float*)d_in[17];
    const int* conn   = (const int*)d_in[18];
    float* out = (float*)d_out;

    cudaFuncSetAttribute(step_kernel, cudaFuncAttributeMaxDynamicSharedMemorySize,
                         SMEM_BYTES);

    init_kernel<<<(BSZ * NN * DD + 255) / 256, 256>>>(h0, m0, w0, id0, dw2, db2);
    for (int t = 0; t < TT; t++) {
        step_kernel<<<NN / NT, 256, SMEM_BYTES>>>(
            cc, hebb, conn, sw1, sb1, sw2, sb2, mw1, mb1, mw2, mb2,
            dw1, db1, out, t, t & 1);
    }
}

// round 9
// speedup vs baseline: 1.3150x; 1.0393x over previous
#include <cuda_runtime.h>
#include <math.h>

#define NN 8192
#define KK 32
#define DD 64
#define DID 32
#define BSZ 4
#define TT 8
#define DSCAN 1024

#define NT 8            // nodes per block
#define ROWS 32         // NT * BSZ rows per block
#define RPA 36          // A pitch (16B-aligned rows, conflict-spread)
#define RPB 36          // B pitch (same; no swizzle needed)

typedef unsigned long long ull;

// Persistent state (allocation-free scratch)
__device__ float g_h[BSZ * NN * DD];
__device__ float g_msgs[2][BSZ * NN * DD];
__device__ float g_wc[BSZ * NN * KK];
__device__ float g_ident[NN * DID];
__device__ float g_dw2p[256 * 128];   // dw2 padded 65 -> 128 cols
__device__ float g_db2p[128];

__device__ __forceinline__ float sigf(float x) { return 1.0f / (1.0f + __expf(-x)); }

__device__ __forceinline__ ull ffma2(ull a, ull b, ull c) {
    ull d;
    asm("fma.rn.f32x2 %0, %1, %2, %3;" : "=l"(d) : "l"(a), "l"(b), "l"(c));
    return d;
}
__device__ __forceinline__ ull pack2(float x) {
    ull p;
    unsigned u = __float_as_uint(x);
    asm("mov.b64 %0, {%1, %2};" : "=l"(p) : "r"(u), "r"(u));
    return p;
}
__device__ __forceinline__ float2 unpack2(ull p) {
    unsigned lo, hi;
    asm("mov.b64 {%0, %1}, %2;" : "=r"(lo), "=r"(hi) : "l"(p));
    return make_float2(__uint_as_float(lo), __uint_as_float(hi));
}
__device__ __forceinline__ ull repack(float x, float y) {
    ull p;
    unsigned a = __float_as_uint(x), b = __float_as_uint(y);
    asm("mov.b64 %0, {%1, %2};" : "=l"(p) : "r"(a), "r"(b));
    return p;
}

// One contiguous k-segment: LEN rows of X starting at xs (pitch PITCH).
template <int CPT, int LEN, int COLS, int UNR, int PITCH>
__device__ __forceinline__ void gemm_seg(const float* xs,
                                         const float* __restrict__ ws,
                                         ull (&acc)[4][CPT]) {
#pragma unroll UNR
    for (int i = 0; i < LEN; i++) {
        ulonglong2 xq0 = *reinterpret_cast<const ulonglong2*>(xs + i * PITCH);
        ulonglong2 xq1 = *reinterpret_cast<const ulonglong2*>(xs + i * PITCH + 4);
        ull xp[4] = {xq0.x, xq0.y, xq1.x, xq1.y};
        float wv[CPT];
        const float* wr = ws + (size_t)i * COLS;
        if (CPT == 4) {
            float4 f = __ldg(reinterpret_cast<const float4*>(wr));
            wv[0] = f.x; wv[1] = f.y; wv[2] = f.z; wv[3] = f.w;
        } else if (CPT == 2) {
            float2 f = __ldg(reinterpret_cast<const float2*>(wr));
            wv[0] = f.x; wv[1] = f.y;
        } else {
            wv[0] = __ldg(wr);
        }
        ull wp[CPT];
#pragma unroll
        for (int j = 0; j < CPT; j++) wp[j] = pack2(wv[j]);
#pragma unroll
        for (int p = 0; p < 4; p++)
#pragma unroll
            for (int j = 0; j < CPT; j++)
                acc[p][j] = ffma2(xp[p], wp[j], acc[p][j]);
    }
}

// Segmented GEMM over up to 4 compile-time (base,len) row segments.
// 8 warps split COLS; lane = 4 row-groups x 8 col-groups; rows packed f32x2.
template <int CPT, int ACT, int COLS, int UNR, bool WSYNC, int IPITCH, int OPITCH,
          int B0, int L0, int B1, int L1, int B2, int L2, int B3, int L3>
__device__ __forceinline__ void gemmS(const float* Xt, const float* __restrict__ W,
                                      const float* __restrict__ bias,
                                      float* Yt, int yoff) {
    const int w = threadIdx.x >> 5;
    const int lane = threadIdx.x & 31;
    const int r0 = (lane >> 3) * 8;
    const int c0 = w * (COLS / 8) + (lane & 7) * CPT;
    ull acc[4][CPT];
#pragma unroll
    for (int p = 0; p < 4; p++)
#pragma unroll
        for (int j = 0; j < CPT; j++) acc[p][j] = 0ull;

    const float* xb = Xt + r0;
    const float* wb = W + c0;
    gemm_seg<CPT, L0, COLS, UNR, IPITCH>(xb + B0 * IPITCH, wb, acc);
    if (L1 > 0) gemm_seg<CPT, L1, COLS, UNR, IPITCH>(xb + B1 * IPITCH, wb + (size_t)L0 * COLS, acc);
    if (L2 > 0) gemm_seg<CPT, L2, COLS, UNR, IPITCH>(xb + B2 * IPITCH, wb + (size_t)(L0 + L1) * COLS, acc);
    if (L3 > 0) gemm_seg<CPT, L3, COLS, UNR, IPITCH>(xb + B3 * IPITCH, wb + (size_t)(L0 + L1 + L2) * COLS, acc);

    if (WSYNC) __syncthreads();

#pragma unroll
    for (int j = 0; j < CPT; j++) {
        float bc = __ldg(bias + c0 + j);
#pragma unroll
        for (int p = 0; p < 4; p++) {
            float2 v = unpack2(acc[p][j]);
            v.x += bc; v.y += bc;
            if (ACT == 1) {
                v.x = v.x * (1.0f / (1.0f + __expf(-v.x)));
                v.y = v.y * (1.0f / (1.0f + __expf(-v.y)));
            } else if (ACT == 2) {
                v.x = tanhf(v.x);
                v.y = tanhf(v.y);
            }
            *reinterpret_cast<ull*>(Yt + (yoff + c0 + j) * OPITCH + r0 + 2 * p) =
                repack(v.x, v.y);
        }
    }
}

// msg layer 2: CPT=1, tanh, reads B, writes g_msgs directly from registers.
__device__ __forceinline__ void gemm_msg2(const float* Bt, const float* __restrict__ W,
                                          const float* __restrict__ bias,
                                          float* __restrict__ gm, int n0) {
    const int w = threadIdx.x >> 5;
    const int lane = threadIdx.x & 31;
    const int r0 = (lane >> 3) * 8;
    const int c0 = w * 8 + (lane & 7);
    ull acc[4][1];
#pragma unroll
    for (int p = 0; p < 4; p++) acc[p][0] = 0ull;
    gemm_seg<1, 256, 64, 8, RPB>(Bt + r0, W + c0, acc);
    float bc = __ldg(bias + c0);
#pragma unroll
    for (int p = 0; p < 4; p++) {
        float2 v = unpack2(acc[p][0]);
        v.x = tanhf(v.x + bc);
        v.y = tanhf(v.y + bc);
        int r = r0 + 2 * p;
        gm[((size_t)(r & 3) * NN + n0 + (r >> 2)) * DD + c0] = v.x;
        gm[((size_t)((r + 1) & 3) * NN + n0 + ((r + 1) >> 2)) * DD + c0] = v.y;
    }
}

__global__ void __launch_bounds__(256, 3) step_kernel(
    const float* __restrict__ cc, const float* __restrict__ hebb,
    const int* __restrict__ conn,
    const float* __restrict__ sw1, const float* __restrict__ sb1,
    const float* __restrict__ sw2, const float* __restrict__ sb2,
    const float* __restrict__ mw1, const float* __restrict__ mb1,
    const float* __restrict__ mw2, const float* __restrict__ mb2,
    const float* __restrict__ dw1, const float* __restrict__ db1,
    float* __restrict__ out, int t, int p) {
    extern __shared__ float sm[];
    float* A = sm;                     // 256*RPA transposed activations
    float* B = A + 256 * RPA;          // 256*RPB hidden / layer-2 out (in-place)
    float* dec = B + 256 * RPB;        // ROWS decay
    // transient (dead after gather, overwritten by mod layer1 output):
    float* wk = B;                     // ROWS*KK sigmoid(w_conn)
    int* idxs = (int*)(B + ROWS * KK); // NT*KK neighbor indices

    const int tid = threadIdx.x;
    const int n0 = blockIdx.x * NT;

    // ---- Phase 0: indices + sigmoid(w_conn) + transposed mod_in fills ----
    // A rows: [0:32] hebbian, [32:96] h, [96:128] ident, [128:192] received,
    //         [192:256] inject
    {
        int ln = tid >> 5, k = tid & 31;
        idxs[tid] = conn[(n0 + ln) * KK + k];
    }
    for (int i = tid; i < ROWS * KK; i += 256) {
        int r = i >> 5, k = i & 31, ln = r >> 2, b = r & 3;
        wk[i] = sigf(g_wc[((size_t)b * NN + n0 + ln) * KK + k]);
    }
    for (int i = tid; i < ROWS * KK; i += 256) {
        int r = i >> 5, j = i & 31, ln = r >> 2, b = r & 3;
        A[j * RPA + r] = hebb[((size_t)b * NN + n0 + ln) * KK + j];
    }
    for (int i = tid; i < ROWS * DD; i += 256) {
        int r = i >> 6, d = i & 63, ln = r >> 2, b = r & 3;
        A[(32 + d) * RPA + r] = g_h[((size_t)b * NN + n0 + ln) * DD + d];
    }
    for (int i = tid; i < ROWS * DID; i += 256) {
        int r = i >> 5, j = i & 31, ln = r >> 2;
        A[(96 + j) * RPA + r] = g_ident[(n0 + ln) * DID + j];
    }
    for (int i = tid; i < ROWS * DD; i += 256) {
        int r = i >> 6, d = i & 63, ln = r >> 2, b = r & 3;
        int n = n0 + ln;
        A[(192 + d) * RPA + r] = cc[((size_t)b * TT + t) * DSCAN + (n >> 9) * DD + d];
    }
    __syncthreads();

    // ---- received = sum_k sigmoid(w) * msgs[neighbor] -> A rows [128:192] ----
    {
        const float* mp = g_msgs[p];
#pragma unroll
        for (int task = tid; task < 512; task += 256) {
            int r = task >> 4;
            int q = task & 15;
            int ln = r >> 2, b = r & 3;
            const float* wrow = wk + r * KK;
            const int* irow = idxs + ln * KK;
            const float* mb = mp + (size_t)b * NN * DD + 4 * q;
            float4 acc = make_float4(0.f, 0.f, 0.f, 0.f);
#pragma unroll 8
            for (int k = 0; k < KK; k++) {
                float wv = wrow[k];
                int nb = irow[k];
                float4 m = __ldcg(reinterpret_cast<const float4*>(mb + (size_t)nb * DD));
                acc.x = fmaf(wv, m.x, acc.x);
                acc.y = fmaf(wv, m.y, acc.y);
                acc.z = fmaf(wv, m.z, acc.z);
                acc.w = fmaf(wv, m.w, acc.w);
            }
            float* dst = A + (128 + 4 * q) * RPA + r;
            dst[0] = acc.x;
            dst[RPA] = acc.y;
            dst[2 * RPA] = acc.z;
            dst[3 * RPA] = acc.w;
        }
    }
    __syncthreads();

    // ---- mod MLP: layer1 A[0:256] -> B; layer2 B -> B[0:128] in-place ----
    gemmS<4, 1, 256, 4, false, RPA, RPB,
          0, 256, 0, 0, 0, 0, 0, 0>(A, dw1, db1, B, 0);
    __syncthreads();
    gemmS<2, 0, 128, 8, true, RPB, RPB,
          0, 256, 0, 0, 0, 0, 0, 0>(B, g_dw2p, g_db2p, B, 0);
    __syncthreads();

    // ---- w_new, decay, identity update; ide2 -> A rows [96:128] ----
    for (int i = tid; i < ROWS * KK; i += 256) {
        int r = i >> 5, k = i & 31, ln = r >> 2, b = r & 3;
        g_wc[((size_t)b * NN + n0 + ln) * KK + k] = B[k * RPB + r];
    }
    if (tid < ROWS) dec[tid] = sigf(B[32 * RPB + tid]);
    {
        int ln = tid >> 5, j = tid & 31;
        const float* cr = B + (33 + j) * RPB + ln * 4;
        float v = g_ident[(n0 + ln) * DID + j] +
                  0.25f * (cr[0] + cr[1] + cr[2] + cr[3]);
        g_ident[(n0 + ln) * DID + j] = v;
        float* ar = A + (96 + j) * RPA + ln * 4;
        ar[0] = v; ar[1] = v; ar[2] = v; ar[3] = v;
    }
    __syncthreads();

    // ---- state MLP: layer1 reads segments [received,inject,h,ide2] of A ----
    gemmS<4, 1, 256, 4, false, RPA, RPB,
          128, 64, 192, 64, 32, 64, 96, 32>(A, sw1, sb1, B, 0);
    __syncthreads();
    gemmS<1, 2, 64, 8, false, RPB, RPA,
          0, 256, 0, 0, 0, 0, 0, 0>(B, sw2, sb2, A, 128);  // tanh -> A[128:192]
    __syncthreads();

    // ---- h_new = decay*h + (1-decay)*tanh -> A rows [192:256], g_h, out ----
    for (int i = tid; i < ROWS * DD; i += 256) {
        int r = i >> 6, d = i & 63, ln = r >> 2, b = r & 3;
        float de = dec[r];
        float hn = de * A[(32 + d) * RPA + r] + (1.0f - de) * A[(128 + d) * RPA + r];
        g_h[((size_t)b * NN + n0 + ln) * DD + d] = hn;
        out[(((size_t)b * TT + t) * NN + n0 + ln) * DD + d] = hn;
        A[(192 + d) * RPA + r] = hn;
    }
    __syncthreads();

    // ---- msg MLP: layer1 reads [h_new, ide2]; layer2 writes g_msgs direct ----
    gemmS<4, 1, 256, 4, false, RPA, RPB,
          192, 64, 96, 32, 0, 0, 0, 0>(A, mw1, mb1, B, 0);
    __syncthreads();
    gemm_msg2(B, mw2, mb2, g_msgs[p ^ 1], n0);
}

__global__ void init_kernel(const float* __restrict__ h0, const float* __restrict__ m0,
                            const float* __restrict__ w0, const float* __restrict__ id0,
                            const float* __restrict__ dw2, const float* __restrict__ db2) {
    size_t i = (size_t)blockIdx.x * blockDim.x + threadIdx.x;
    if (i < (size_t)BSZ * NN * DD) {
        g_h[i] = h0[i];
        g_msgs[0][i] = m0[i];
    }
    if (i < (size_t)BSZ * NN * KK) g_wc[i] = w0[i];
    if (i < (size_t)NN * DID) g_ident[i] = id0[i];
    if (i < 256 * 128) {
        int r = (int)i >> 7, c = (int)i & 127;
        g_dw2p[i] = (c < 65) ? dw2[r * 65 + c] : 0.0f;
    }
    if (i < 128) g_db2p[i] = (i < 65) ? db2[i] : 0.0f;
}

#define SMEM_BYTES ((256 * RPA + 256 * RPB + ROWS) * 4)

extern "C" void kernel_launch(void* const* d_in, const int* in_sizes, int n_in,
                              void* d_out, int out_size) {
    const float* cc   = (const float*)d_in[0];
    const float* h0   = (const float*)d_in[1];
    const float* m0   = (const float*)d_in[2];
    const float* w0   = (const float*)d_in[3];
    const float* hebb = (const float*)d_in[4];
    const float* id0  = (const float*)d_in[5];
    const float* sw1  = (const float*)d_in[6];
    const float* sb1  = (const float*)d_in[7];
    const float* sw2  = (const float*)d_in[8];
    const float* sb2  = (const float*)d_in[9];
    const float* mw1  = (const float*)d_in[10];
    const float* mb1  = (const float*)d_in[11];
    const float* mw2  = (const float*)d_in[12];
    const float* mb2  = (const float*)d_in[13];
    const float* dw1  = (const float*)d_in[14];
    const float* db1  = (const float*)d_in[15];
    const float* dw2  = (const float*)d_in[16];
    const float* db2  = (const float*)d_in[17];
    const int* conn   = (const int*)d_in[18];
    float* out = (float*)d_out;

    cudaFuncSetAttribute(step_kernel, cudaFuncAttributeMaxDynamicSharedMemorySize,
                         SMEM_BYTES);

    init_kernel<<<(BSZ * NN * DD + 255) / 256, 256>>>(h0, m0, w0, id0, dw2, db2);
    for (int t = 0; t < TT; t++) {
        step_kernel<<<NN / NT, 256, SMEM_BYTES>>>(
            cc, hebb, conn, sw1, sb1, sw2, sb2, mw1, mb1, mw2, mb2,
            dw1, db1, out, t, t & 1);
    }
}

// round 10
// speedup vs baseline: 1.3281x; 1.0099x over previous
#include <cuda_runtime.h>
#include <math.h>

#define NN 8192
#define KK 32
#define DD 64
#define DID 32
#define BSZ 4
#define TT 8
#define DSCAN 1024

#define NT 8            // nodes per block
#define ROWS 32         // NT * BSZ rows per block
#define RPA 36          // A pitch (16B-aligned rows, conflict-spread)
#define RPB 36          // B pitch

typedef unsigned long long ull;

// Persistent state (allocation-free scratch)
__device__ float g_h[BSZ * NN * DD];
__device__ float g_msgs[2][BSZ * NN * DD];
__device__ float g_wc[BSZ * NN * KK];
__device__ float g_ident[NN * DID];
__device__ float g_dw2p[256 * 64];    // dw2 cols 0..63 (w_new, decay, ident 0..30)
__device__ float g_dw2c[256];         // dw2 col 64 (ident 31)
__device__ float g_db2p[64];
__device__ float g_db2c;

__device__ __forceinline__ float sigf(float x) { return 1.0f / (1.0f + __expf(-x)); }

__device__ __forceinline__ ull ffma2(ull a, ull b, ull c) {
    ull d;
    asm("fma.rn.f32x2 %0, %1, %2, %3;" : "=l"(d) : "l"(a), "l"(b), "l"(c));
    return d;
}
__device__ __forceinline__ ull pack2(float x) {
    ull p;
    unsigned u = __float_as_uint(x);
    asm("mov.b64 %0, {%1, %2};" : "=l"(p) : "r"(u), "r"(u));
    return p;
}
__device__ __forceinline__ float2 unpack2(ull p) {
    unsigned lo, hi;
    asm("mov.b64 {%0, %1}, %2;" : "=r"(lo), "=r"(hi) : "l"(p));
    return make_float2(__uint_as_float(lo), __uint_as_float(hi));
}
__device__ __forceinline__ ull repack(float x, float y) {
    ull p;
    unsigned a = __float_as_uint(x), b = __float_as_uint(y);
    asm("mov.b64 %0, {%1, %2};" : "=l"(p) : "r"(a), "r"(b));
    return p;
}

// One contiguous k-segment: LEN rows of X starting at xs (pitch PITCH).
template <int CPT, int LEN, int COLS, int UNR, int PITCH>
__device__ __forceinline__ void gemm_seg(const float* xs,
                                         const float* __restrict__ ws,
                                         ull (&acc)[4][CPT]) {
#pragma unroll UNR
    for (int i = 0; i < LEN; i++) {
        ulonglong2 xq0 = *reinterpret_cast<const ulonglong2*>(xs + i * PITCH);
        ulonglong2 xq1 = *reinterpret_cast<const ulonglong2*>(xs + i * PITCH + 4);
        ull xp[4] = {xq0.x, xq0.y, xq1.x, xq1.y};
        float wv[CPT];
        const float* wr = ws + (size_t)i * COLS;
        if (CPT == 4) {
            float4 f = __ldg(reinterpret_cast<const float4*>(wr));
            wv[0] = f.x; wv[1] = f.y; wv[2] = f.z; wv[3] = f.w;
        } else if (CPT == 2) {
            float2 f = __ldg(reinterpret_cast<const float2*>(wr));
            wv[0] = f.x; wv[1] = f.y;
        } else {
            wv[0] = __ldg(wr);
        }
        ull wp[CPT];
#pragma unroll
        for (int j = 0; j < CPT; j++) wp[j] = pack2(wv[j]);
#pragma unroll
        for (int p = 0; p < 4; p++)
#pragma unroll
            for (int j = 0; j < CPT; j++)
                acc[p][j] = ffma2(xp[p], wp[j], acc[p][j]);
    }
}

// Segmented GEMM over up to 4 compile-time (base,len) row segments.
// 8 warps split COLS; lane = 4 row-groups x 8 col-groups; rows packed f32x2.
template <int CPT, int ACT, int COLS, int UNR, bool WSYNC, int IPITCH, int OPITCH,
          int B0, int L0, int B1, int L1, int B2, int L2, int B3, int L3>
__device__ __forceinline__ void gemmS(const float* Xt, const float* __restrict__ W,
                                      const float* __restrict__ bias,
                                      float* Yt, int yoff) {
    const int w = threadIdx.x >> 5;
    const int lane = threadIdx.x & 31;
    const int r0 = (lane >> 3) * 8;
    const int c0 = w * (COLS / 8) + (lane & 7) * CPT;
    ull acc[4][CPT];
#pragma unroll
    for (int p = 0; p < 4; p++)
#pragma unroll
        for (int j = 0; j < CPT; j++) acc[p][j] = 0ull;

    const float* xb = Xt + r0;
    const float* wb = W + c0;
    gemm_seg<CPT, L0, COLS, UNR, IPITCH>(xb + B0 * IPITCH, wb, acc);
    if (L1 > 0) gemm_seg<CPT, L1, COLS, UNR, IPITCH>(xb + B1 * IPITCH, wb + (size_t)L0 * COLS, acc);
    if (L2 > 0) gemm_seg<CPT, L2, COLS, UNR, IPITCH>(xb + B2 * IPITCH, wb + (size_t)(L0 + L1) * COLS, acc);
    if (L3 > 0) gemm_seg<CPT, L3, COLS, UNR, IPITCH>(xb + B3 * IPITCH, wb + (size_t)(L0 + L1 + L2) * COLS, acc);

    if (WSYNC) __syncthreads();

#pragma unroll
    for (int j = 0; j < CPT; j++) {
        float bc = __ldg(bias + c0 + j);
#pragma unroll
        for (int p = 0; p < 4; p++) {
            float2 v = unpack2(acc[p][j]);
            v.x += bc; v.y += bc;
            if (ACT == 1) {
                v.x = v.x * (1.0f / (1.0f + __expf(-v.x)));
                v.y = v.y * (1.0f / (1.0f + __expf(-v.y)));
            } else if (ACT == 2) {
                v.x = tanhf(v.x);
                v.y = tanhf(v.y);
            }
            *reinterpret_cast<ull*>(Yt + (yoff + c0 + j) * OPITCH + r0 + 2 * p) =
                repack(v.x, v.y);
        }
    }
}

// msg layer 2: CPT=1, tanh, reads B, writes g_msgs directly from registers.
__device__ __forceinline__ void gemm_msg2(const float* Bt, const float* __restrict__ W,
                                          const float* __restrict__ bias,
                                          float* __restrict__ gm, int n0) {
    const int w = threadIdx.x >> 5;
    const int lane = threadIdx.x & 31;
    const int r0 = (lane >> 3) * 8;
    const int c0 = w * 8 + (lane & 7);
    ull acc[4][1];
#pragma unroll
    for (int p = 0; p < 4; p++) acc[p][0] = 0ull;
    gemm_seg<1, 256, 64, 8, RPB>(Bt + r0, W + c0, acc);
    float bc = __ldg(bias + c0);
#pragma unroll
    for (int p = 0; p < 4; p++) {
        float2 v = unpack2(acc[p][0]);
        v.x = tanhf(v.x + bc);
        v.y = tanhf(v.y + bc);
        int r = r0 + 2 * p;
        gm[((size_t)(r & 3) * NN + n0 + (r >> 2)) * DD + c0] = v.x;
        gm[((size_t)((r + 1) & 3) * NN + n0 + ((r + 1) >> 2)) * DD + c0] = v.y;
    }
}

__global__ void __launch_bounds__(256, 3) step_kernel(
    const float* __restrict__ cc, const float* __restrict__ hebb,
    const int* __restrict__ conn,
    const float* __restrict__ sw1, const float* __restrict__ sb1,
    const float* __restrict__ sw2, const float* __restrict__ sb2,
    const float* __restrict__ mw1, const float* __restrict__ mb1,
    const float* __restrict__ mw2, const float* __restrict__ mb2,
    const float* __restrict__ dw1, const float* __restrict__ db1,
    float* __restrict__ out, int t, int p) {
    extern __shared__ float sm[];
    float* A = sm;                     // 256*RPA transposed activations
    float* B = A + 256 * RPA;          // 256*RPB hidden / layer-2 out (in-place)
    float* dec = B + 256 * RPB;        // ROWS decay
    float* xsc = dec + ROWS;           // 32 floats: mod_out col 64 (ident delta 31)
    // transient (dead after gather, overwritten by mod layer1 output):
    float* wk = B;                     // ROWS*KK sigmoid(w_conn)
    int* idxs = (int*)(B + ROWS * KK); // NT*KK neighbor indices

    const int tid = threadIdx.x;
    const int n0 = blockIdx.x * NT;

    // ---- Phase 0: indices + sigmoid(w_conn) + transposed mod_in fills ----
    // A rows: [0:32] hebbian, [32:96] h, [96:128] ident, [128:192] received,
    //         [192:256] inject
    {
        int ln = tid >> 5, k = tid & 31;
        idxs[tid] = conn[(n0 + ln) * KK + k];
    }
    for (int i = tid; i < ROWS * KK; i += 256) {
        int r = i >> 5, k = i & 31, ln = r >> 2, b = r & 3;
        wk[i] = sigf(g_wc[((size_t)b * NN + n0 + ln) * KK + k]);
    }
    for (int i = tid; i < ROWS * KK; i += 256) {
        int r = i >> 5, j = i & 31, ln = r >> 2, b = r & 3;
        A[j * RPA + r] = hebb[((size_t)b * NN + n0 + ln) * KK + j];
    }
    for (int i = tid; i < ROWS * DD; i += 256) {
        int r = i >> 6, d = i & 63, ln = r >> 2, b = r & 3;
        A[(32 + d) * RPA + r] = g_h[((size_t)b * NN + n0 + ln) * DD + d];
    }
    for (int i = tid; i < ROWS * DID; i += 256) {
        int r = i >> 5, j = i & 31, ln = r >> 2;
        A[(96 + j) * RPA + r] = g_ident[(n0 + ln) * DID + j];
    }
    for (int i = tid; i < ROWS * DD; i += 256) {
        int r = i >> 6, d = i & 63, ln = r >> 2, b = r & 3;
        int n = n0 + ln;
        A[(192 + d) * RPA + r] = cc[((size_t)b * TT + t) * DSCAN + (n >> 9) * DD + d];
    }
    __syncthreads();

    // ---- received = sum_k sigmoid(w) * msgs[neighbor] -> A rows [128:192] ----
    {
        const float* mp = g_msgs[p];
#pragma unroll
        for (int task = tid; task < 512; task += 256) {
            int r = task >> 4;
            int q = task & 15;
            int ln = r >> 2, b = r & 3;
            const float* wrow = wk + r * KK;
            const int* irow = idxs + ln * KK;
            const float* mb = mp + (size_t)b * NN * DD + 4 * q;
            float4 acc = make_float4(0.f, 0.f, 0.f, 0.f);
#pragma unroll 8
            for (int k = 0; k < KK; k++) {
                float wv = wrow[k];
                int nb = irow[k];
                float4 m = __ldcg(reinterpret_cast<const float4*>(mb + (size_t)nb * DD));
                acc.x = fmaf(wv, m.x, acc.x);
                acc.y = fmaf(wv, m.y, acc.y);
                acc.z = fmaf(wv, m.z, acc.z);
                acc.w = fmaf(wv, m.w, acc.w);
            }
            float* dst = A + (128 + 4 * q) * RPA + r;
            dst[0] = acc.x;
            dst[RPA] = acc.y;
            dst[2 * RPA] = acc.z;
            dst[3 * RPA] = acc.w;
        }
    }
    __syncthreads();

    // ---- mod MLP layer1: A[0:256] -> B (silu) ----
    gemmS<4, 1, 256, 4, false, RPA, RPB,
          0, 256, 0, 0, 0, 0, 0, 0>(A, dw1, db1, B, 0);
    __syncthreads();

    // ---- mod layer2 extra column (dw2 col 64 = ident delta 31): GEMV ----
    // 8 threads per output row; lane-staggered k order -> conflict-free LDS.
    {
        int r = tid >> 3, j = tid & 7;
        float acc = 0.0f;
#pragma unroll 8
        for (int kk = 0; kk < 32; kk++) {
            int k = j * 32 + ((kk + j) & 31);
            acc = fmaf(B[k * RPB + r], __ldg(g_dw2c + k), acc);
        }
        acc += __shfl_down_sync(0xffffffffu, acc, 4);
        acc += __shfl_down_sync(0xffffffffu, acc, 2);
        acc += __shfl_down_sync(0xffffffffu, acc, 1);
        if (j == 0) xsc[r] = acc + g_db2c;
    }

    // ---- mod layer2 main: B[0:256] -> B rows [0:64) in-place (WSYNC) ----
    gemmS<1, 0, 64, 8, true, RPB, RPB,
          0, 256, 0, 0, 0, 0, 0, 0>(B, g_dw2p, g_db2p, B, 0);
    __syncthreads();

    // ---- w_new, decay, identity update; ide2 -> A rows [96:128] ----
    for (int i = tid; i < ROWS * KK; i += 256) {
        int r = i >> 5, k = i & 31, ln = r >> 2, b = r & 3;
        g_wc[((size_t)b * NN + n0 + ln) * KK + k] = B[k * RPB + r];
    }
    if (tid < ROWS) dec[tid] = sigf(B[32 * RPB + tid]);
    {
        int ln = tid >> 5, j = tid & 31;
        float s;
        if (j < 31) {
            const float* cr = B + (33 + j) * RPB + ln * 4;
            s = cr[0] + cr[1] + cr[2] + cr[3];
        } else {
            s = xsc[ln * 4] + xsc[ln * 4 + 1] + xsc[ln * 4 + 2] + xsc[ln * 4 + 3];
        }
        float v = g_ident[(n0 + ln) * DID + j] + 0.25f * s;
        g_ident[(n0 + ln) * DID + j] = v;
        float* ar = A + (96 + j) * RPA + ln * 4;
        ar[0] = v; ar[1] = v; ar[2] = v; ar[3] = v;
    }
    __syncthreads();

    // ---- state MLP: layer1 reads segments [received,inject,h,ide2] of A ----
    gemmS<4, 1, 256, 4, false, RPA, RPB,
          128, 64, 192, 64, 32, 64, 96, 32>(A, sw1, sb1, B, 0);
    __syncthreads();
    gemmS<1, 2, 64, 8, false, RPB, RPA,
          0, 256, 0, 0, 0, 0, 0, 0>(B, sw2, sb2, A, 128);  // tanh -> A[128:192]
    __syncthreads();

    // ---- h_new = decay*h + (1-decay)*tanh -> A rows [192:256], g_h, out ----
    for (int i = tid; i < ROWS * DD; i += 256) {
        int r = i >> 6, d = i & 63, ln = r >> 2, b = r & 3;
        float de = dec[r];
        float hn = de * A[(32 + d) * RPA + r] + (1.0f - de) * A[(128 + d) * RPA + r];
        g_h[((size_t)b * NN + n0 + ln) * DD + d] = hn;
        out[(((size_t)b * TT + t) * NN + n0 + ln) * DD + d] = hn;
        A[(192 + d) * RPA + r] = hn;
    }
    __syncthreads();

    // ---- msg MLP: layer1 reads [h_new, ide2]; layer2 writes g_msgs direct ----
    gemmS<4, 1, 256, 4, false, RPA, RPB,
          192, 64, 96, 32, 0, 0, 0, 0>(A, mw1, mb1, B, 0);
    __syncthreads();
    gemm_msg2(B, mw2, mb2, g_msgs[p ^ 1], n0);
}

__global__ void init_kernel(const float* __restrict__ h0, const float* __restrict__ m0,
                            const float* __restrict__ w0, const float* __restrict__ id0,
                            const float* __restrict__ dw2, const float* __restrict__ db2) {
    size_t i = (size_t)blockIdx.x * blockDim.x + threadIdx.x;
    if (i < (size_t)BSZ * NN * DD) {
        g_h[i] = h0[i];
        g_msgs[0][i] = m0[i];
    }
    if (i < (size_t)BSZ * NN * KK) g_wc[i] = w0[i];
    if (i < (size_t)NN * DID) g_ident[i] = id0[i];
    if (i < 256 * 64) {
        int r = (int)i >> 6, c = (int)i & 63;
        g_dw2p[i] = dw2[r * 65 + c];
    }
    if (i < 256) g_dw2c[i] = dw2[i * 65 + 64];
    if (i < 64) g_db2p[i] = db2[i];
    if (i == 0) g_db2c = db2[64];
}

#define SMEM_BYTES ((256 * RPA + 256 * RPB + ROWS + 32) * 4)

extern "C" void kernel_launch(void* const* d_in, const int* in_sizes, int n_in,
                              void* d_out, int out_size) {
    const float* cc   = (const float*)d_in[0];
    const float* h0   = (const float*)d_in[1];
    const float* m0   = (const float*)d_in[2];
    const float* w0   = (const float*)d_in[3];
    const float* hebb = (const float*)d_in[4];
    const float* id0  = (const float*)d_in[5];
    const float* sw1  = (const float*)d_in[6];
    const float* sb1  = (const float*)d_in[7];
    const float* sw2  = (const float*)d_in[8];
    const float* sb2  = (const float*)d_in[9];
    const float* mw1  = (const float*)d_in[10];
    const float* mb1  = (const float*)d_in[11];
    const float* mw2  = (const float*)d_in[12];
    const float* mb2  = (const float*)d_in[13];
    const float* dw1  = (const float*)d_in[14];
    const float* db1  = (const float*)d_in[15];
    const float* dw2  = (const float*)d_in[16];
    const float* db2  = (const float*)d_in[17];
    const int* conn   = (const int*)d_in[18];
    float* out = (float*)d_out;

    cudaFuncSetAttribute(step_kernel, cudaFuncAttributeMaxDynamicSharedMemorySize,
                         SMEM_BYTES);

    init_kernel<<<(BSZ * NN * DD + 255) / 256, 256>>>(h0, m0, w0, id0, dw2, db2);
    for (int t = 0; t < TT; t++) {
        step_kernel<<<NN / NT, 256, SMEM_BYTES>>>(
            cc, hebb, conn, sw1, sb1, sw2, sb2, mw1, mb1, mw2, mb2,
            dw1, db1, out, t, t & 1);
    }
}